// round 7
// baseline (speedup 1.0000x reference)
#include <cuda_runtime.h>
#include <cstdint>
#include <cstddef>

#define B_ 16
#define C_ 512
#define N_ 4096
#define K_ 32
#define NS_ 8                 // K3 n-splits (512 n each)
#define CT_ 4                 // K3 c-tiles (128 c each)

// Scratch (device globals — allocation-free rule)
__device__ float    g_A[B_ * K_ * N_];                    // [b][k][n]  8 MB
__device__ float    g_part[B_ * NS_ * CT_ * K_ * 128];    // 8 MB partials
__device__ uint32_t g_cwt[K_ * C_];                       // tf32 codewords
__device__ float    g_c2[K_];
__device__ float    g_as[B_ * K_ * 32];                   // per-ntile Asum partials

__device__ __forceinline__ uint32_t tf32_of(float a) {
    uint32_t r;
    asm("{ .reg .b32 t; cvt.rna.tf32.f32 t, %1; mov.b32 %0, t; }" : "=r"(r) : "f"(a));
    return r;
}
__device__ __forceinline__ void mma16888(float* d, const uint32_t* a, const uint32_t* b) {
    asm volatile(
        "mma.sync.aligned.m16n8k8.row.col.f32.tf32.tf32.f32 "
        "{%0,%1,%2,%3}, {%4,%5,%6,%7}, {%8,%9}, {%0,%1,%2,%3};"
        : "+f"(d[0]), "+f"(d[1]), "+f"(d[2]), "+f"(d[3])
        : "r"(a[0]), "r"(a[1]), "r"(a[2]), "r"(a[3]), "r"(b[0]), "r"(b[1]));
}

// =====================================================================
// K0: cw -> tf32 scratch + c2.  grid 32 (one block per k), 128 threads.
// =====================================================================
__global__ void k0_prep(const float* __restrict__ cw) {
    __shared__ float red[4];
    const int k = blockIdx.x, tid = threadIdx.x;
    float4 v = ((const float4*)(cw + k * C_))[tid];
    uint4 u = make_uint4(tf32_of(v.x), tf32_of(v.y), tf32_of(v.z), tf32_of(v.w));
    ((uint4*)(g_cwt + k * C_))[tid] = u;
    float a0 = __uint_as_float(u.x), a1 = __uint_as_float(u.y);
    float a2 = __uint_as_float(u.z), a3 = __uint_as_float(u.w);
    float s = a0 * a0 + a1 * a1 + a2 * a2 + a3 * a3;
    #pragma unroll
    for (int o = 16; o; o >>= 1) s += __shfl_down_sync(0xffffffffu, s, o);
    if ((tid & 31) == 0) red[tid >> 5] = s;
    __syncthreads();
    if (tid == 0) g_c2[k] = (red[0] + red[1]) + (red[2] + red[3]);
}

// =====================================================================
// K1: logits + softmax via mma.sync tf32.  cw B-fragments read straight
// from g_cwt (L1-resident, 64 KB) -> smem is only the x double-buffer.
// grid (32 n-tiles, 16 b), 256 threads (8 warps, warp owns 16 n).
// static smem ~40.7 KB -> 3-4 CTAs/SM.
// Also emits per-CTA Asum partials to g_as.
// =====================================================================
__global__ void __launch_bounds__(256) k1_softmax(const float* __restrict__ x,
                                                  const float* __restrict__ scale) {
    __shared__ uint32_t x_s[2][32 * 136];     // 34816 B (reused as Ao after)
    __shared__ float sq_s[256 * 4];           //  4096 B
    __shared__ float x2_s[128];
    __shared__ float sc_s[K_], c2_s[K_];
    __shared__ float as_s[8][K_];

    const int tid  = threadIdx.x;
    const int lane = tid & 31, w = tid >> 5;
    const int b    = blockIdx.y;
    const int n0   = blockIdx.x * 128;
    const int ar0  = lane >> 2, an0 = lane & 3;

    if (tid < 32) { sc_s[tid] = scale[tid]; c2_s[tid] = g_c2[tid]; }

    // ---- mainloop: 16 chunks of 32 c ----
    const float* xg = x + (size_t)b * C_ * N_ + n0;
    const uint32_t* __restrict__ cwt = g_cwt;
    const int cst = tid >> 5;              // c sub-row 0..7
    const int nq4 = lane * 4;              // n offset (4 n per thread)

    float sq[4] = {0.f, 0.f, 0.f, 0.f};
    float acc[4][4];
    #pragma unroll
    for (int nt = 0; nt < 4; nt++)
        #pragma unroll
        for (int j = 0; j < 4; j++) acc[nt][j] = 0.f;

    float4 xr[4];
    #pragma unroll
    for (int j = 0; j < 4; j++)
        xr[j] = *(const float4*)(xg + (size_t)(cst + 8 * j) * N_ + nq4);

    for (int ch = 0; ch < 16; ch++) {
        uint32_t* xb = x_s[ch & 1];
        #pragma unroll
        for (int j = 0; j < 4; j++) {
            float4 v = xr[j];
            sq[0] += v.x * v.x; sq[1] += v.y * v.y;
            sq[2] += v.z * v.z; sq[3] += v.w * v.w;
            *(uint4*)(xb + (cst + 8 * j) * 136 + nq4) =
                make_uint4(tf32_of(v.x), tf32_of(v.y), tf32_of(v.z), tf32_of(v.w));
        }
        __syncthreads();
        if (ch < 15) {
            #pragma unroll
            for (int j = 0; j < 4; j++)
                xr[j] = *(const float4*)(xg +
                    (size_t)((ch + 1) * 32 + cst + 8 * j) * N_ + nq4);
        }
        // compute: 4 k-steps of 8 c; B-frags from global (L1 hits)
        #pragma unroll
        for (int ks = 0; ks < 4; ks++) {
            const int cb = ks * 8;
            uint32_t af[4];
            const uint32_t* ap = xb + (cb + an0) * 136 + 16 * w + ar0;
            af[0] = ap[0];
            af[1] = ap[8];
            af[2] = ap[4 * 136];
            af[3] = ap[4 * 136 + 8];
            const int gc = ch * 32 + cb + an0;
            #pragma unroll
            for (int nt = 0; nt < 4; nt++) {
                uint32_t bf[2];
                const uint32_t* bp = cwt + (8 * nt + ar0) * C_ + gc;
                bf[0] = bp[0];
                bf[1] = bp[4];
                mma16888(acc[nt], af, bf);
            }
        }
        __syncthreads();
    }

    // ---- x2 reduce (exact fp32) ----
    *(float4*)(sq_s + tid * 4) = make_float4(sq[0], sq[1], sq[2], sq[3]);
    __syncthreads();
    if (tid < 128) {
        float s = 0.f;
        #pragma unroll
        for (int g = 0; g < 8; g++) s += sq_s[(g * 32 + (tid >> 2)) * 4 + (tid & 3)];
        x2_s[tid] = s;
    }
    __syncthreads();

    // ---- logits + softmax ----
    const float x2r0 = x2_s[16 * w + ar0];
    const float x2r1 = x2_s[16 * w + ar0 + 8];
    float lg0[8], lg1[8];
    float m0 = -1e30f, m1 = -1e30f;
    #pragma unroll
    for (int nt = 0; nt < 4; nt++) {
        #pragma unroll
        for (int j = 0; j < 2; j++) {
            const int k = 8 * nt + 2 * an0 + j;
            const float sck = sc_s[k], c2k = c2_s[k];
            float a = sck * (x2r0 - 2.f * acc[nt][j]     + c2k);
            float c = sck * (x2r1 - 2.f * acc[nt][2 + j] + c2k);
            lg0[nt * 2 + j] = a; lg1[nt * 2 + j] = c;
            m0 = fmaxf(m0, a); m1 = fmaxf(m1, c);
        }
    }
    m0 = fmaxf(m0, __shfl_xor_sync(0xffffffffu, m0, 1));
    m0 = fmaxf(m0, __shfl_xor_sync(0xffffffffu, m0, 2));
    m1 = fmaxf(m1, __shfl_xor_sync(0xffffffffu, m1, 1));
    m1 = fmaxf(m1, __shfl_xor_sync(0xffffffffu, m1, 2));
    float s0 = 0.f, s1 = 0.f;
    #pragma unroll
    for (int i = 0; i < 8; i++) {
        lg0[i] = __expf(lg0[i] - m0); s0 += lg0[i];
        lg1[i] = __expf(lg1[i] - m1); s1 += lg1[i];
    }
    s0 += __shfl_xor_sync(0xffffffffu, s0, 1);
    s0 += __shfl_xor_sync(0xffffffffu, s0, 2);
    s1 += __shfl_xor_sync(0xffffffffu, s1, 1);
    s1 += __shfl_xor_sync(0xffffffffu, s1, 2);
    const float inv0 = 1.f / s0, inv1 = 1.f / s1;

    // ---- Asum partials: reduce over this CTA's 128 n ----
    float akp[8];
    #pragma unroll
    for (int i = 0; i < 8; i++) akp[i] = lg0[i] * inv0 + lg1[i] * inv1;
    #pragma unroll
    for (int off = 4; off < 32; off <<= 1)
        #pragma unroll
        for (int i = 0; i < 8; i++)
            akp[i] += __shfl_xor_sync(0xffffffffu, akp[i], off);
    if (ar0 == 0) {
        #pragma unroll
        for (int nt = 0; nt < 4; nt++)
            #pragma unroll
            for (int j = 0; j < 2; j++)
                as_s[w][8 * nt + 2 * an0 + j] = akp[nt * 2 + j];
    }

    // ---- transpose A through smem (reuse x_s), coalesced STG ----
    float* Ao = (float*)x_s;                      // [32 k][132 n-pad]
    #pragma unroll
    for (int nt = 0; nt < 4; nt++) {
        #pragma unroll
        for (int j = 0; j < 2; j++) {
            const int k = 8 * nt + 2 * an0 + j;
            Ao[k * 132 + 16 * w + ar0]     = lg0[nt * 2 + j] * inv0;
            Ao[k * 132 + 16 * w + ar0 + 8] = lg1[nt * 2 + j] * inv1;
        }
    }
    __syncthreads();
    if (tid < 32) {
        float s = 0.f;
        #pragma unroll
        for (int ww = 0; ww < 8; ww++) s += as_s[ww][tid];
        g_as[(b * K_ + tid) * 32 + blockIdx.x] = s;
    }
    float* ag = g_A + (size_t)(b * K_) * N_ + n0;
    #pragma unroll
    for (int t = 0; t < 4; t++) {
        int f = tid + t * 256;                    // 0..1023
        int k = f >> 5, nq = (f & 31) * 4;
        *(float4*)(ag + (size_t)k * N_ + nq) = *(float4*)(Ao + k * 132 + nq);
    }
}

// =====================================================================
// K3: enc partial via mma.sync tf32 (m16n8k8).  (unchanged, known-good)
// D[32k x 128c] += sum_n A[k,n] * x[c,n]   over 512 n per CTA.
// =====================================================================
__global__ void __launch_bounds__(256) k3_enc(const float* __restrict__ x) {
    __shared__ uint32_t x_s[2][128 * 36];   // [c][n] tf32, pad 36
    __shared__ uint32_t A_s[2][32 * 36];    // [k][n] tf32, pad 36

    const int tid   = threadIdx.x;
    const int lane  = tid & 31, w = tid >> 5;
    const int ctile = blockIdx.x;
    const int ns    = blockIdx.y;
    const int b     = blockIdx.z;
    const int cwarp = w * 16;

    const float* xg = x   + ((size_t)(b * C_) + ctile * 128) * N_;
    const float* ag = g_A + ((size_t)b * K_) * N_;
    const int nb0 = ns * 512;

    float acc[2][2][4];
    #pragma unroll
    for (int mt = 0; mt < 2; mt++)
        #pragma unroll
        for (int ct = 0; ct < 2; ct++)
            #pragma unroll
            for (int j = 0; j < 4; j++) acc[mt][ct][j] = 0.f;

    const int xc = tid >> 1;
    const int xh = tid & 1;
    const int ak = tid >> 3;
    const int aq = tid & 7;

    float4 xr[4], ar;
    {
        const float* xp = xg + (size_t)xc * N_ + nb0 + xh * 16;
        #pragma unroll
        for (int j = 0; j < 4; j++) xr[j] = *(const float4*)(xp + 4 * j);
        ar = *(const float4*)(ag + (size_t)ak * N_ + nb0 + aq * 4);
    }

    for (int ch = 0; ch < 16; ch++) {
        const int buf = ch & 1;
        {
            uint32_t* xd = &x_s[buf][xc * 36 + xh * 16];
            #pragma unroll
            for (int j = 0; j < 4; j++) {
                uint4 v = make_uint4(tf32_of(xr[j].x), tf32_of(xr[j].y),
                                     tf32_of(xr[j].z), tf32_of(xr[j].w));
                *(uint4*)(xd + 4 * j) = v;
            }
            uint4 av = make_uint4(tf32_of(ar.x), tf32_of(ar.y),
                                  tf32_of(ar.z), tf32_of(ar.w));
            *(uint4*)(&A_s[buf][ak * 36 + aq * 4]) = av;
        }
        __syncthreads();

        if (ch < 15) {
            const int nbase = nb0 + (ch + 1) * 32;
            const float* xp = xg + (size_t)xc * N_ + nbase + xh * 16;
            #pragma unroll
            for (int j = 0; j < 4; j++) xr[j] = *(const float4*)(xp + 4 * j);
            ar = *(const float4*)(ag + (size_t)ak * N_ + nbase + aq * 4);
        }

        const uint32_t* As = A_s[buf];
        const uint32_t* Xs = x_s[buf];
        const int ar0 = lane >> 2;
        const int an0 = lane & 3;
        #pragma unroll
        for (int ks = 0; ks < 4; ks++) {
            const int nk = ks * 8;
            uint32_t af[2][4], bf[2][2];
            #pragma unroll
            for (int mt = 0; mt < 2; mt++) {
                const uint32_t* ap = As + (mt * 16 + ar0) * 36 + nk + an0;
                af[mt][0] = ap[0];
                af[mt][1] = ap[8 * 36];
                af[mt][2] = ap[4];
                af[mt][3] = ap[8 * 36 + 4];
            }
            #pragma unroll
            for (int ct = 0; ct < 2; ct++) {
                const uint32_t* bp = Xs + (cwarp + ct * 8 + ar0) * 36 + nk + an0;
                bf[ct][0] = bp[0];
                bf[ct][1] = bp[4];
            }
            #pragma unroll
            for (int mt = 0; mt < 2; mt++)
                #pragma unroll
                for (int ct = 0; ct < 2; ct++)
                    mma16888(acc[mt][ct], af[mt], bf[ct]);
        }
        __syncthreads();
    }

    float* pb = g_part + (((size_t)(b * NS_ + ns) * CT_ + ctile) << 12);
    const int dr = lane >> 2;
    const int dc = (lane & 3) * 2;
    #pragma unroll
    for (int mt = 0; mt < 2; mt++) {
        #pragma unroll
        for (int ct = 0; ct < 2; ct++) {
            const int c0 = cwarp + ct * 8 + dc;
            const int r0 = mt * 16 + dr;
            *(float2*)(pb + r0 * 128 + c0) =
                make_float2(acc[mt][ct][0], acc[mt][ct][1]);
            *(float2*)(pb + (r0 + 8) * 128 + c0) =
                make_float2(acc[mt][ct][2], acc[mt][ct][3]);
        }
    }
}

// =====================================================================
// K4: per (b,k): Asum from g_as partials + combine + subtract Asum*cw.
// =====================================================================
__global__ void k4_final(float* __restrict__ out, const float* __restrict__ cw) {
    __shared__ float s_asum;
    const int bk  = blockIdx.x;
    const int b   = bk >> 5, k = bk & 31;
    const int tid = threadIdx.x;

    if (tid < 32) {
        float v = g_as[bk * 32 + tid];
        #pragma unroll
        for (int o = 16; o; o >>= 1) v += __shfl_down_sync(0xffffffffu, v, o);
        if (tid == 0) s_asum = v;
    }
    __syncthreads();
    const float asum = s_asum;

    #pragma unroll
    for (int j = 0; j < 4; j++) {
        const int c  = tid + j * 128;
        const int ct = c >> 7, cl = c & 127;
        float v = 0.f;
        #pragma unroll
        for (int sp = 0; sp < NS_; sp++)
            v += g_part[(((size_t)(b * NS_ + sp) * CT_ + ct) << 12) + k * 128 + cl];
        out[(size_t)bk * C_ + c] = v - asum * cw[k * C_ + c];
    }
}

// =====================================================================
extern "C" void kernel_launch(void* const* d_in, const int* in_sizes, int n_in,
                              void* d_out, int out_size) {
    const float* x     = (const float*)d_in[0];
    const float* cw    = (const float*)d_in[1];
    const float* scale = (const float*)d_in[2];
    float* out = (float*)d_out;

    k0_prep<<<K_, 128>>>(cw);
    k1_softmax<<<dim3(32, 16), 256>>>(x, scale);
    k3_enc<<<dim3(CT_, NS_, B_), 256>>>(x);
    k4_final<<<B_ * K_, 128>>>(out, cw);
}

// round 8
// speedup vs baseline: 1.5805x; 1.5805x over previous
#include <cuda_runtime.h>
#include <cstdint>
#include <cstddef>

#define B_ 16
#define C_ 512
#define N_ 4096
#define K_ 32
#define NS_ 8                 // K3 n-splits (512 n each)
#define CT_ 4                 // K3 c-tiles (128 c each)

// Scratch (device globals — allocation-free rule)
__device__ float g_A[B_ * K_ * N_];                       // [b][k][n]  8 MB
__device__ float g_part[B_ * NS_ * CT_ * K_ * 128];       // 8 MB partials
__device__ float g_as[B_ * K_ * 32];                      // per-ntile Asum partials

__device__ __forceinline__ uint32_t tf32_of(float a) {
    uint32_t r;
    asm("{ .reg .b32 t; cvt.rna.tf32.f32 t, %1; mov.b32 %0, t; }" : "=r"(r) : "f"(a));
    return r;
}
__device__ __forceinline__ void mma16888(float* d, const uint32_t* a, const uint32_t* b) {
    asm volatile(
        "mma.sync.aligned.m16n8k8.row.col.f32.tf32.tf32.f32 "
        "{%0,%1,%2,%3}, {%4,%5,%6,%7}, {%8,%9}, {%0,%1,%2,%3};"
        : "+f"(d[0]), "+f"(d[1]), "+f"(d[2]), "+f"(d[3])
        : "r"(a[0]), "r"(a[1]), "r"(a[2]), "r"(a[3]), "r"(b[0]), "r"(b[1]));
}

// =====================================================================
// K1: logits + softmax via mma.sync tf32.
// GEMM: D[128 n x 32 k] = sum_c x[n,c] * cw[k,c];  x2 kept exact fp32.
// grid (32 n-tiles, 16 b), 256 threads (8 warps, warp owns 16 n).
// Single-sync pipelined mainloop: store chunk ch+1 / prefetch ch+2 while
// computing chunk ch.  Also emits per-CTA Asum partials to g_as.
// dyn smem layout (bytes):
//   cw_s  [32][516] tf32   @0       66048
//   x_s 2x[32][136] tf32   @66048   34816   (reused as A_out [32][132] after)
//   sq_s  [256][4]  f32    @100864   4096
//   x2_s  [128]     f32    @104960    512
//   sc_s  [32]      f32    @105472    128
//   c2_s  [32]      f32    @105600    128
//   as_s  [8][32]   f32    @105728   1024   -> total 106752
// =====================================================================
#define K1_SMEM 106752

__global__ void __launch_bounds__(256) k1_softmax(const float* __restrict__ x,
                                                  const float* __restrict__ cw,
                                                  const float* __restrict__ scale) {
    extern __shared__ char sm[];
    uint32_t* cw_s = (uint32_t*)(sm);
    uint32_t* x_s  = (uint32_t*)(sm + 66048);
    float*    sq_s = (float*)(sm + 100864);
    float*    x2_s = (float*)(sm + 104960);
    float*    sc_s = (float*)(sm + 105472);
    float*    c2_s = (float*)(sm + 105600);
    float*    as_s = (float*)(sm + 105728);    // [8][32]

    const int tid  = threadIdx.x;
    const int lane = tid & 31, w = tid >> 5;
    const int b    = blockIdx.y;
    const int n0   = blockIdx.x * 128;
    const int ar0  = lane >> 2, an0 = lane & 3;

    // ---- stage cw -> cw_s[k][c] tf32 (stride 516) ----
    const float4* cwg = (const float4*)cw;
    #pragma unroll
    for (int t = 0; t < 16; t++) {
        int f = tid + t * 256;             // 0..4095
        int k = f >> 7, cq = f & 127;
        float4 v = cwg[f];
        uint4 u = make_uint4(tf32_of(v.x), tf32_of(v.y), tf32_of(v.z), tf32_of(v.w));
        *(uint4*)(cw_s + k * 516 + cq * 4) = u;
    }
    if (tid < 32) sc_s[tid] = scale[tid];
    __syncthreads();
    if (tid < 32) {                        // c2 from tf32 cw (error negligible)
        float s = 0.f;
        const uint4* row = (const uint4*)(cw_s + tid * 516);
        #pragma unroll 4
        for (int q = 0; q < 128; q++) {
            uint4 u = row[q];
            float a0 = __uint_as_float(u.x), a1 = __uint_as_float(u.y);
            float a2 = __uint_as_float(u.z), a3 = __uint_as_float(u.w);
            s += a0 * a0 + a1 * a1 + a2 * a2 + a3 * a3;
        }
        c2_s[tid] = s;
    }

    // ---- mainloop: 16 chunks of 32 c, single sync per chunk ----
    const float* xg = x + (size_t)b * C_ * N_ + n0;
    const int cst = tid >> 5;              // c sub-row 0..7
    const int nq4 = lane * 4;              // n offset (4 n per thread)

    float sq[4] = {0.f, 0.f, 0.f, 0.f};
    float acc[4][4];
    #pragma unroll
    for (int nt = 0; nt < 4; nt++)
        #pragma unroll
        for (int j = 0; j < 4; j++) acc[nt][j] = 0.f;

    float4 xr[4];
    // load chunk 0, store to buf 0
    #pragma unroll
    for (int j = 0; j < 4; j++)
        xr[j] = *(const float4*)(xg + (size_t)(cst + 8 * j) * N_ + nq4);
    {
        uint32_t* xb = x_s;                 // buf 0
        #pragma unroll
        for (int j = 0; j < 4; j++) {
            float4 v = xr[j];
            sq[0] += v.x * v.x; sq[1] += v.y * v.y;
            sq[2] += v.z * v.z; sq[3] += v.w * v.w;
            *(uint4*)(xb + (cst + 8 * j) * 136 + nq4) =
                make_uint4(tf32_of(v.x), tf32_of(v.y), tf32_of(v.z), tf32_of(v.w));
        }
    }
    // load chunk 1
    #pragma unroll
    for (int j = 0; j < 4; j++)
        xr[j] = *(const float4*)(xg + (size_t)(32 + cst + 8 * j) * N_ + nq4);
    __syncthreads();

    for (int ch = 0; ch < 16; ch++) {
        // store chunk ch+1 into buf (ch+1)&1  (that buffer's compute finished
        // at iteration ch-1; separated by the trailing sync)
        if (ch < 15) {
            uint32_t* xb = x_s + ((ch + 1) & 1) * (32 * 136);
            #pragma unroll
            for (int j = 0; j < 4; j++) {
                float4 v = xr[j];
                sq[0] += v.x * v.x; sq[1] += v.y * v.y;
                sq[2] += v.z * v.z; sq[3] += v.w * v.w;
                *(uint4*)(xb + (cst + 8 * j) * 136 + nq4) =
                    make_uint4(tf32_of(v.x), tf32_of(v.y), tf32_of(v.z), tf32_of(v.w));
            }
        }
        // prefetch chunk ch+2 (2 compute phases to land)
        if (ch < 14) {
            #pragma unroll
            for (int j = 0; j < 4; j++)
                xr[j] = *(const float4*)(xg +
                    (size_t)((ch + 2) * 32 + cst + 8 * j) * N_ + nq4);
        }
        // compute chunk ch from buf ch&1: 4 k-steps of 8 c
        const uint32_t* xb = x_s + (ch & 1) * (32 * 136);
        #pragma unroll
        for (int ks = 0; ks < 4; ks++) {
            const int cb = ks * 8;
            uint32_t af[4];
            const uint32_t* ap = xb + (cb + an0) * 136 + 16 * w + ar0;
            af[0] = ap[0];
            af[1] = ap[8];
            af[2] = ap[4 * 136];
            af[3] = ap[4 * 136 + 8];
            const int gc = ch * 32 + cb + an0;
            #pragma unroll
            for (int nt = 0; nt < 4; nt++) {
                uint32_t bf[2];
                const uint32_t* bp = cw_s + (8 * nt + ar0) * 516 + gc;
                bf[0] = bp[0];
                bf[1] = bp[4];
                mma16888(acc[nt], af, bf);
            }
        }
        __syncthreads();
    }

    // ---- x2 reduce (exact fp32) ----
    *(float4*)(sq_s + tid * 4) = make_float4(sq[0], sq[1], sq[2], sq[3]);
    __syncthreads();
    if (tid < 128) {
        float s = 0.f;
        #pragma unroll
        for (int g = 0; g < 8; g++) s += sq_s[(g * 32 + (tid >> 2)) * 4 + (tid & 3)];
        x2_s[tid] = s;
    }
    __syncthreads();

    // ---- logits + softmax ----
    const float x2r0 = x2_s[16 * w + ar0];
    const float x2r1 = x2_s[16 * w + ar0 + 8];
    float lg0[8], lg1[8];
    float m0 = -1e30f, m1 = -1e30f;
    #pragma unroll
    for (int nt = 0; nt < 4; nt++) {
        #pragma unroll
        for (int j = 0; j < 2; j++) {
            const int k = 8 * nt + 2 * an0 + j;
            const float sck = sc_s[k], c2k = c2_s[k];
            float a = sck * (x2r0 - 2.f * acc[nt][j]     + c2k);
            float c = sck * (x2r1 - 2.f * acc[nt][2 + j] + c2k);
            lg0[nt * 2 + j] = a; lg1[nt * 2 + j] = c;
            m0 = fmaxf(m0, a); m1 = fmaxf(m1, c);
        }
    }
    m0 = fmaxf(m0, __shfl_xor_sync(0xffffffffu, m0, 1));
    m0 = fmaxf(m0, __shfl_xor_sync(0xffffffffu, m0, 2));
    m1 = fmaxf(m1, __shfl_xor_sync(0xffffffffu, m1, 1));
    m1 = fmaxf(m1, __shfl_xor_sync(0xffffffffu, m1, 2));
    float s0 = 0.f, s1 = 0.f;
    #pragma unroll
    for (int i = 0; i < 8; i++) {
        lg0[i] = __expf(lg0[i] - m0); s0 += lg0[i];
        lg1[i] = __expf(lg1[i] - m1); s1 += lg1[i];
    }
    s0 += __shfl_xor_sync(0xffffffffu, s0, 1);
    s0 += __shfl_xor_sync(0xffffffffu, s0, 2);
    s1 += __shfl_xor_sync(0xffffffffu, s1, 1);
    s1 += __shfl_xor_sync(0xffffffffu, s1, 2);
    const float inv0 = 1.f / s0, inv1 = 1.f / s1;

    // ---- Asum partials: reduce over this CTA's 128 n ----
    float akp[8];
    #pragma unroll
    for (int i = 0; i < 8; i++) akp[i] = lg0[i] * inv0 + lg1[i] * inv1;
    #pragma unroll
    for (int off = 4; off < 32; off <<= 1)
        #pragma unroll
        for (int i = 0; i < 8; i++)
            akp[i] += __shfl_xor_sync(0xffffffffu, akp[i], off);
    if (ar0 == 0) {
        #pragma unroll
        for (int nt = 0; nt < 4; nt++)
            #pragma unroll
            for (int j = 0; j < 2; j++)
                as_s[w * 32 + 8 * nt + 2 * an0 + j] = akp[nt * 2 + j];
    }

    // ---- transpose A through smem (reuse x_s), coalesced STG ----
    float* Ao = (float*)x_s;                      // [32 k][132 n-pad]
    #pragma unroll
    for (int nt = 0; nt < 4; nt++) {
        #pragma unroll
        for (int j = 0; j < 2; j++) {
            const int k = 8 * nt + 2 * an0 + j;
            Ao[k * 132 + 16 * w + ar0]     = lg0[nt * 2 + j] * inv0;
            Ao[k * 132 + 16 * w + ar0 + 8] = lg1[nt * 2 + j] * inv1;
        }
    }
    __syncthreads();
    if (tid < 32) {
        float s = 0.f;
        #pragma unroll
        for (int ww = 0; ww < 8; ww++) s += as_s[ww * 32 + tid];
        g_as[(b * K_ + tid) * 32 + blockIdx.x] = s;
    }
    float* ag = g_A + (size_t)(b * K_) * N_ + n0;
    #pragma unroll
    for (int t = 0; t < 4; t++) {
        int f = tid + t * 256;                    // 0..1023
        int k = f >> 5, nq = (f & 31) * 4;
        *(float4*)(ag + (size_t)k * N_ + nq) = *(float4*)(Ao + k * 132 + nq);
    }
}

// =====================================================================
// K3: enc partial via mma.sync tf32 (m16n8k8).  (unchanged, known-good)
// D[32k x 128c] += sum_n A[k,n] * x[c,n]   over 512 n per CTA.
// =====================================================================
__global__ void __launch_bounds__(256) k3_enc(const float* __restrict__ x) {
    __shared__ uint32_t x_s[2][128 * 36];   // [c][n] tf32, pad 36
    __shared__ uint32_t A_s[2][32 * 36];    // [k][n] tf32, pad 36

    const int tid   = threadIdx.x;
    const int lane  = tid & 31, w = tid >> 5;
    const int ctile = blockIdx.x;
    const int ns    = blockIdx.y;
    const int b     = blockIdx.z;
    const int cwarp = w * 16;

    const float* xg = x   + ((size_t)(b * C_) + ctile * 128) * N_;
    const float* ag = g_A + ((size_t)b * K_) * N_;
    const int nb0 = ns * 512;

    float acc[2][2][4];
    #pragma unroll
    for (int mt = 0; mt < 2; mt++)
        #pragma unroll
        for (int ct = 0; ct < 2; ct++)
            #pragma unroll
            for (int j = 0; j < 4; j++) acc[mt][ct][j] = 0.f;

    const int xc = tid >> 1;
    const int xh = tid & 1;
    const int ak = tid >> 3;
    const int aq = tid & 7;

    float4 xr[4], ar;
    {
        const float* xp = xg + (size_t)xc * N_ + nb0 + xh * 16;
        #pragma unroll
        for (int j = 0; j < 4; j++) xr[j] = *(const float4*)(xp + 4 * j);
        ar = *(const float4*)(ag + (size_t)ak * N_ + nb0 + aq * 4);
    }

    for (int ch = 0; ch < 16; ch++) {
        const int buf = ch & 1;
        {
            uint32_t* xd = &x_s[buf][xc * 36 + xh * 16];
            #pragma unroll
            for (int j = 0; j < 4; j++) {
                uint4 v = make_uint4(tf32_of(xr[j].x), tf32_of(xr[j].y),
                                     tf32_of(xr[j].z), tf32_of(xr[j].w));
                *(uint4*)(xd + 4 * j) = v;
            }
            uint4 av = make_uint4(tf32_of(ar.x), tf32_of(ar.y),
                                  tf32_of(ar.z), tf32_of(ar.w));
            *(uint4*)(&A_s[buf][ak * 36 + aq * 4]) = av;
        }
        __syncthreads();

        if (ch < 15) {
            const int nbase = nb0 + (ch + 1) * 32;
            const float* xp = xg + (size_t)xc * N_ + nbase + xh * 16;
            #pragma unroll
            for (int j = 0; j < 4; j++) xr[j] = *(const float4*)(xp + 4 * j);
            ar = *(const float4*)(ag + (size_t)ak * N_ + nbase + aq * 4);
        }

        const uint32_t* As = A_s[buf];
        const uint32_t* Xs = x_s[buf];
        const int ar0 = lane >> 2;
        const int an0 = lane & 3;
        #pragma unroll
        for (int ks = 0; ks < 4; ks++) {
            const int nk = ks * 8;
            uint32_t af[2][4], bf[2][2];
            #pragma unroll
            for (int mt = 0; mt < 2; mt++) {
                const uint32_t* ap = As + (mt * 16 + ar0) * 36 + nk + an0;
                af[mt][0] = ap[0];
                af[mt][1] = ap[8 * 36];
                af[mt][2] = ap[4];
                af[mt][3] = ap[8 * 36 + 4];
            }
            #pragma unroll
            for (int ct = 0; ct < 2; ct++) {
                const uint32_t* bp = Xs + (cwarp + ct * 8 + ar0) * 36 + nk + an0;
                bf[ct][0] = bp[0];
                bf[ct][1] = bp[4];
            }
            #pragma unroll
            for (int mt = 0; mt < 2; mt++)
                #pragma unroll
                for (int ct = 0; ct < 2; ct++)
                    mma16888(acc[mt][ct], af[mt], bf[ct]);
        }
        __syncthreads();
    }

    float* pb = g_part + (((size_t)(b * NS_ + ns) * CT_ + ctile) << 12);
    const int dr = lane >> 2;
    const int dc = (lane & 3) * 2;
    #pragma unroll
    for (int mt = 0; mt < 2; mt++) {
        #pragma unroll
        for (int ct = 0; ct < 2; ct++) {
            const int c0 = cwarp + ct * 8 + dc;
            const int r0 = mt * 16 + dr;
            *(float2*)(pb + r0 * 128 + c0) =
                make_float2(acc[mt][ct][0], acc[mt][ct][1]);
            *(float2*)(pb + (r0 + 8) * 128 + c0) =
                make_float2(acc[mt][ct][2], acc[mt][ct][3]);
        }
    }
}

// =====================================================================
// K4: per (b,k): Asum from g_as partials + combine + subtract Asum*cw.
// =====================================================================
__global__ void k4_final(float* __restrict__ out, const float* __restrict__ cw) {
    __shared__ float s_asum;
    const int bk  = blockIdx.x;
    const int b   = bk >> 5, k = bk & 31;
    const int tid = threadIdx.x;

    if (tid < 32) {
        float v = g_as[bk * 32 + tid];
        #pragma unroll
        for (int o = 16; o; o >>= 1) v += __shfl_down_sync(0xffffffffu, v, o);
        if (tid == 0) s_asum = v;
    }
    __syncthreads();
    const float asum = s_asum;

    #pragma unroll
    for (int j = 0; j < 4; j++) {
        const int c  = tid + j * 128;
        const int ct = c >> 7, cl = c & 127;
        float v = 0.f;
        #pragma unroll
        for (int sp = 0; sp < NS_; sp++)
            v += g_part[(((size_t)(b * NS_ + sp) * CT_ + ct) << 12) + k * 128 + cl];
        out[(size_t)bk * C_ + c] = v - asum * cw[k * C_ + c];
    }
}

// =====================================================================
extern "C" void kernel_launch(void* const* d_in, const int* in_sizes, int n_in,
                              void* d_out, int out_size) {
    const float* x     = (const float*)d_in[0];
    const float* cw    = (const float*)d_in[1];
    const float* scale = (const float*)d_in[2];
    float* out = (float*)d_out;

    cudaFuncSetAttribute(k1_softmax, cudaFuncAttributeMaxDynamicSharedMemorySize, K1_SMEM);

    k1_softmax<<<dim3(32, 16), 256, K1_SMEM>>>(x, cw, scale);
    k3_enc<<<dim3(CT_, NS_, B_), 256>>>(x);
    k4_final<<<B_ * K_, 128>>>(out, cw);
}